// round 12
// baseline (speedup 1.0000x reference)
#include <cuda_runtime.h>
#include <cuda_fp16.h>
#include <math.h>
#include <stdint.h>

#define Nn 4096
#define NHEADS 8
#define SQFC 0.42466090f   // sqrt(SCALE * log2(e))
#define FULLM 0xffffffffu

// fp16 projections (K1/K2 pre-scaled by SQFC)
__device__ __half g_K1H[Nn * 512];
__device__ __half g_K2H[Nn * 512];
__device__ __half g_V1H[Nn * 512];
__device__ __half g_V2H[Nn * 512];
// fp16 partial attention outputs: slab z = dir*2 + ks
__device__ __half g_Oph[4][Nn * 512];
// per-slab row-sum partials (direct store, no atomics/zeroing)
__device__ float g_sumP[4][NHEADS * Nn];
__device__ float g_rsum[NHEADS * Nn];   // holds 1/rowsum after recip
__device__ float g_csum[NHEADS * Nn];   // holds 1/colsum after recip

struct Ptrs {
    const float* p[16];
};

__device__ __forceinline__ void mma_f16(float c[4],
                                        uint32_t a0, uint32_t a1, uint32_t a2, uint32_t a3,
                                        uint32_t b0, uint32_t b1) {
    asm volatile(
        "mma.sync.aligned.m16n8k16.row.col.f32.f16.f16.f32 "
        "{%0,%1,%2,%3}, {%4,%5,%6,%7}, {%8,%9}, {%0,%1,%2,%3};\n"
        : "+f"(c[0]), "+f"(c[1]), "+f"(c[2]), "+f"(c[3])
        : "r"(a0), "r"(a1), "r"(a2), "r"(a3), "r"(b0), "r"(b1));
}

// f16-accumulator variant: D/C are 2 packed f16x2 regs
__device__ __forceinline__ void mma_f16h(uint32_t c[2],
                                         uint32_t a0, uint32_t a1, uint32_t a2, uint32_t a3,
                                         uint32_t b0, uint32_t b1) {
    asm volatile(
        "mma.sync.aligned.m16n8k16.row.col.f16.f16.f16.f16 "
        "{%0,%1}, {%2,%3,%4,%5}, {%6,%7}, {%0,%1};\n"
        : "+r"(c[0]), "+r"(c[1])
        : "r"(a0), "r"(a1), "r"(a2), "r"(a3), "r"(b0), "r"(b1));
}

__device__ __forceinline__ void ldm_x4(uint32_t r[4], const void* ptr) {
    uint32_t addr = (uint32_t)__cvta_generic_to_shared(ptr);
    asm volatile("ldmatrix.sync.aligned.m8n8.x4.shared.b16 {%0,%1,%2,%3}, [%4];"
                 : "=r"(r[0]), "=r"(r[1]), "=r"(r[2]), "=r"(r[3]) : "r"(addr));
}

__device__ __forceinline__ void ldm_x4_trans(uint32_t r[4], const void* ptr) {
    uint32_t addr = (uint32_t)__cvta_generic_to_shared(ptr);
    asm volatile("ldmatrix.sync.aligned.m8n8.x4.trans.shared.b16 {%0,%1,%2,%3}, [%4];"
                 : "=r"(r[0]), "=r"(r[1]), "=r"(r[2]), "=r"(r[3]) : "r"(addr));
}

__device__ __forceinline__ void cp16(void* smem_dst, const void* gsrc) {
    uint32_t d = (uint32_t)__cvta_generic_to_shared(smem_dst);
    asm volatile("cp.async.cg.shared.global [%0], [%1], 16;" :: "r"(d), "l"(gsrc));
}

__device__ __forceinline__ uint32_t ex2p(uint32_t h2) {
    uint32_t r;
    asm("ex2.approx.f16x2 %0, %1;" : "=r"(r) : "r"(h2));
    return r;
}

__device__ __forceinline__ uint4 pack8h(float4 v0, float4 v1) {
    uint4 u;
    __half2* h = (__half2*)&u;
    h[0] = __floats2half2_rn(v0.x, v0.y);
    h[1] = __floats2half2_rn(v0.z, v0.w);
    h[2] = __floats2half2_rn(v1.x, v1.y);
    h[3] = __floats2half2_rn(v1.z, v1.w);
    return u;
}

// ---------------------------------------------------------------------------
// merge row-sum partials -> reciprocals
// ---------------------------------------------------------------------------
__global__ void recip_kernel() {
    int i = blockIdx.x * 256 + threadIdx.x;   // 32768
    g_rsum[i] = 1.0f / (g_sumP[0][i] + g_sumP[1][i]);
    g_csum[i] = 1.0f / (g_sumP[2][i] + g_sumP[3][i]);
}

// ---------------------------------------------------------------------------
// Projection (fp16 mma): C = A @ W + bias -> fp16; K1/K2 scaled by SQFC.
// grid (8, 32, 4), 256 thr.
// ---------------------------------------------------------------------------
__global__ __launch_bounds__(256) void proj_f16_kernel(Ptrs in) {
    const float *A, *W, *bias;
    __half* C;
    float sc;
    switch (blockIdx.z) {
        case 0: A = in.p[0]; W = in.p[4];  bias = in.p[5];  C = g_K1H; sc = SQFC; break;
        case 1: A = in.p[1]; W = in.p[6];  bias = in.p[7];  C = g_V1H; sc = 1.0f; break;
        case 2: A = in.p[2]; W = in.p[8];  bias = in.p[9];  C = g_K2H; sc = SQFC; break;
        default:A = in.p[3]; W = in.p[10]; bias = in.p[11]; C = g_V2H; sc = 1.0f; break;
    }
    __shared__ __half As[128 * 72];
    __shared__ __half Ws[64 * 72];

    const int tid = threadIdx.x;
    const int lane = tid & 31, wid = tid >> 5;
    const int q = lane & 3, g = lane >> 2;
    const int row0 = blockIdx.y * 128;
    const int col0 = blockIdx.x * 64;
    const int brow = ((lane >> 3) & 1) * 8 + (lane & 7);
    const int bcoff = (lane >> 4) * 8;
    const int arow = wid * 16 + (lane & 7) + ((lane >> 3) & 1) * 8;
    const int acoff = (lane >> 4) * 8;

    float o[8][4];
#pragma unroll
    for (int nt = 0; nt < 8; nt++)
#pragma unroll
        for (int j = 0; j < 4; j++) o[nt][j] = 0.f;

    for (int k0 = 0; k0 < 256; k0 += 64) {
        __syncthreads();
#pragma unroll
        for (int it = 0; it < 4; it++) {
            int j = tid + it * 256;
            int rr = j >> 3, c8 = j & 7;
            const float* src = &A[(row0 + rr) * 256 + k0 + c8 * 8];
            *(uint4*)&As[rr * 72 + c8 * 8] =
                pack8h(*(const float4*)src, *(const float4*)(src + 4));
        }
#pragma unroll
        for (int it = 0; it < 2; it++) {
            int j = tid + it * 256;
            int rr = j >> 3, c8 = j & 7;
            const float* src = &W[(k0 + rr) * 512 + col0 + c8 * 8];
            *(uint4*)&Ws[rr * 72 + c8 * 8] =
                pack8h(*(const float4*)src, *(const float4*)(src + 4));
        }
        __syncthreads();
#pragma unroll
        for (int kk = 0; kk < 4; kk++) {
            uint32_t a[4];
            ldm_x4(a, As + arow * 72 + kk * 16 + acoff);
#pragma unroll
            for (int dtp = 0; dtp < 4; dtp++) {
                uint32_t b[4];
                ldm_x4_trans(b, Ws + (kk * 16 + brow) * 72 + dtp * 16 + bcoff);
                mma_f16(o[2 * dtp],     a[0], a[1], a[2], a[3], b[0], b[1]);
                mma_f16(o[2 * dtp + 1], a[0], a[1], a[2], a[3], b[2], b[3]);
            }
        }
    }

    const int r = row0 + wid * 16 + g;
#pragma unroll
    for (int nt = 0; nt < 8; nt++) {
        int c = col0 + nt * 8 + 2 * q;
        float b0 = bias[c], b1 = bias[c + 1];
        __half2 h0 = __floats2half2_rn((o[nt][0] + b0) * sc, (o[nt][1] + b1) * sc);
        __half2 h1 = __floats2half2_rn((o[nt][2] + b0) * sc, (o[nt][3] + b1) * sc);
        *(uint32_t*)&C[r * 512 + c] = *(uint32_t*)&h0;
        *(uint32_t*)&C[(r + 8) * 512 + c] = *(uint32_t*)&h1;
    }
}

// ---------------------------------------------------------------------------
// Fused dual attention: f16-accum S AND PV mmas (PV promoted to f32 per iter).
// grid (32, 8, 4): z = dir*2 + ks. 4-stage cp.async pipeline, 1 block-sync/iter.
// ---------------------------------------------------------------------------
__global__ __launch_bounds__(256, 2) void fused_dir_kernel() {
    extern __shared__ __half sm[];
    __half* Ps = sm;                 // [128][72], warp-private rows; Q staging at init
    __half* Kb = sm + 9216;          // 4 x [64][72]
    __half* Vb = sm + 9216 + 4 * 4608;
    uint32_t* PsU = (uint32_t*)sm;   // stride 36 words

    const int n0 = blockIdx.x * 128;
    const int head = blockIdx.y;
    const int hc = head * 64;
    const int z = blockIdx.z;
    const int dir = z >> 1;
    const int ks = z & 1;

    const __half* Qg = dir ? g_K2H : g_K1H;
    const __half* Kg = dir ? g_K1H : g_K2H;
    const __half* Vg = dir ? g_V1H : g_V2H;

    const int tid = threadIdx.x;
    const int lane = tid & 31, wid = tid >> 5;
    const int q = lane & 3, g = lane >> 2;
    const int arow_lm = wid * 16 + (lane & 7) + ((lane >> 3) & 1) * 8;
    const int acoff = (lane >> 4) * 8;
    const int brow2 = ((lane >> 3) & 1) * 8 + (lane & 7);
    const int bcoff = (lane >> 4) * 8;
    const int arow = wid * 16 + g;

    // ---- stage Q, build A-fragments ----
#pragma unroll
    for (int it = 0; it < 4; it++) {
        int j = tid + it * 256;
        int rr = j >> 3, c8 = j & 7;
        cp16(Ps + rr * 72 + c8 * 8, Qg + (n0 + rr) * 512 + hc + c8 * 8);
    }
    asm volatile("cp.async.commit_group;" ::: "memory");
    asm volatile("cp.async.wait_group 0;" ::: "memory");
    __syncthreads();

    uint32_t af[4][4];
#pragma unroll
    for (int kk = 0; kk < 4; kk++)
        ldm_x4(af[kk], Ps + arow_lm * 72 + kk * 16 + acoff);
    __syncthreads();   // Ps free

    auto issue = [&](int s) {
        const int m0 = (ks * 32 + s) * 64;
        __half* Kd = Kb + (s & 3) * 4608;
        __half* Vd = Vb + (s & 3) * 4608;
#pragma unroll
        for (int it = 0; it < 2; it++) {
            int j = tid + it * 256;
            int rr = j >> 3, c8 = j & 7;
            cp16(Kd + rr * 72 + c8 * 8, Kg + (m0 + rr) * 512 + hc + c8 * 8);
            cp16(Vd + rr * 72 + c8 * 8, Vg + (m0 + rr) * 512 + hc + c8 * 8);
        }
        asm volatile("cp.async.commit_group;" ::: "memory");
    };

    issue(0);
    issue(1);
    issue(2);

    float o[8][4];
#pragma unroll
    for (int dt = 0; dt < 8; dt++)
#pragma unroll
        for (int j = 0; j < 4; j++) o[dt][j] = 0.f;
    float rloc0 = 0.f, rloc1 = 0.f;

    for (int i = 0; i < 32; i++) {
        if (i < 30)       asm volatile("cp.async.wait_group 2;" ::: "memory");
        else if (i == 30) asm volatile("cp.async.wait_group 1;" ::: "memory");
        else              asm volatile("cp.async.wait_group 0;" ::: "memory");
        __syncthreads();   // stage i visible; slot (i-1)&3 free; prev Ps reads done

        if (i + 3 < 32) issue(i + 3);

        const __half* Kc = Kb + (i & 3) * 4608;
        const __half* Vc = Vb + (i & 3) * 4608;

        // ---- S (f16 accum, packed) + exp -> warp-private Ps rows ----
#pragma unroll
        for (int nt2 = 0; nt2 < 4; nt2++) {
            uint32_t s0[2] = {0u, 0u};
            uint32_t s1[2] = {0u, 0u};
#pragma unroll
            for (int kk = 0; kk < 4; kk++) {
                uint32_t bq[4];
                ldm_x4(bq, Kc + (nt2 * 16 + brow2) * 72 + kk * 16 + bcoff);
                mma_f16h(s0, af[kk][0], af[kk][1], af[kk][2], af[kk][3], bq[0], bq[2]);
                mma_f16h(s1, af[kk][0], af[kk][1], af[kk][2], af[kk][3], bq[1], bq[3]);
            }
            uint32_t pA01 = ex2p(s0[0]);
            uint32_t pA23 = ex2p(s0[1]);
            uint32_t pB01 = ex2p(s1[0]);
            uint32_t pB23 = ex2p(s1[1]);
            __half2 hA = __hadd2(*(__half2*)&pA01, *(__half2*)&pB01);
            __half2 hB = __hadd2(*(__half2*)&pA23, *(__half2*)&pB23);
            float2 fA = __half22float2(hA);
            float2 fB = __half22float2(hB);
            rloc0 += fA.x + fA.y;
            rloc1 += fB.x + fB.y;
            PsU[arow * 36 + (2 * nt2) * 4 + q] = pA01;
            PsU[(arow + 8) * 36 + (2 * nt2) * 4 + q] = pA23;
            PsU[arow * 36 + (2 * nt2 + 1) * 4 + q] = pB01;
            PsU[(arow + 8) * 36 + (2 * nt2 + 1) * 4 + q] = pB23;
        }
        __syncwarp();   // own-warp Ps rows visible to own-warp ldsm

        // ---- o += Ps(own 16 rows x 64) @ V(64x64): f16 accum, f32 promote ----
        uint32_t oh[8][2];
#pragma unroll
        for (int dt = 0; dt < 8; dt++) { oh[dt][0] = 0u; oh[dt][1] = 0u; }
#pragma unroll
        for (int kc = 0; kc < 4; kc++) {
            uint32_t a[4];
            ldm_x4(a, Ps + arow_lm * 72 + kc * 16 + acoff);
#pragma unroll
            for (int dtp = 0; dtp < 4; dtp++) {
                uint32_t b[4];
                ldm_x4_trans(b, Vc + (kc * 16 + brow2) * 72 + dtp * 16 + bcoff);
                mma_f16h(oh[2 * dtp],     a[0], a[1], a[2], a[3], b[0], b[1]);
                mma_f16h(oh[2 * dtp + 1], a[0], a[1], a[2], a[3], b[2], b[3]);
            }
        }
#pragma unroll
        for (int dt = 0; dt < 8; dt++) {
            float2 f0 = __half22float2(*(__half2*)&oh[dt][0]);
            float2 f1 = __half22float2(*(__half2*)&oh[dt][1]);
            o[dt][0] += f0.x; o[dt][1] += f0.y;
            o[dt][2] += f1.x; o[dt][3] += f1.y;
        }
    }

    // ---- flush partial o (fp16 direct store) + row-sum partials ----
    {
        const int rN = n0 + arow;
        __half* Og = g_Oph[z] + rN * 512 + hc;
#pragma unroll
        for (int dt = 0; dt < 8; dt++) {
            __half2 h0 = __floats2half2_rn(o[dt][0], o[dt][1]);
            __half2 h1 = __floats2half2_rn(o[dt][2], o[dt][3]);
            *(uint32_t*)&Og[dt * 8 + 2 * q] = *(uint32_t*)&h0;
            *(uint32_t*)&Og[8 * 512 + dt * 8 + 2 * q] = *(uint32_t*)&h1;
        }
    }
    rloc0 += __shfl_xor_sync(FULLM, rloc0, 1);
    rloc0 += __shfl_xor_sync(FULLM, rloc0, 2);
    rloc1 += __shfl_xor_sync(FULLM, rloc1, 1);
    rloc1 += __shfl_xor_sync(FULLM, rloc1, 2);
    if (q == 0) {
        g_sumP[z][head * Nn + n0 + arow] = rloc0;
        g_sumP[z][head * Nn + n0 + arow + 8] = rloc1;
    }
}

// ---------------------------------------------------------------------------
// Output GEMM (fp16 mma): out = ((S0+S1) * inv) @ Wo + bias. grid (4, 32, 2).
// ---------------------------------------------------------------------------
__global__ __launch_bounds__(256) void outproj_f16_kernel(Ptrs in, float* out) {
    const __half *S0h, *S1h;
    const float *inv, *W, *bias;
    float* C;
    if (blockIdx.z == 0) {
        S0h = g_Oph[2]; S1h = g_Oph[3]; inv = g_csum;
        W = in.p[12]; bias = in.p[13]; C = out;
    } else {
        S0h = g_Oph[0]; S1h = g_Oph[1]; inv = g_rsum;
        W = in.p[14]; bias = in.p[15]; C = out + Nn * 256;
    }
    __shared__ __half As[128 * 72];
    __shared__ __half Ws[64 * 72];

    const int tid = threadIdx.x;
    const int lane = tid & 31, wid = tid >> 5;
    const int q = lane & 3, g = lane >> 2;
    const int row0 = blockIdx.y * 128;
    const int col0 = blockIdx.x * 64;
    const int brow = ((lane >> 3) & 1) * 8 + (lane & 7);
    const int bcoff = (lane >> 4) * 8;
    const int arow = wid * 16 + (lane & 7) + ((lane >> 3) & 1) * 8;
    const int acoff = (lane >> 4) * 8;

    float o[8][4];
#pragma unroll
    for (int nt = 0; nt < 8; nt++)
#pragma unroll
        for (int j = 0; j < 4; j++) o[nt][j] = 0.f;

    for (int k0 = 0; k0 < 512; k0 += 64) {
        const int head = k0 >> 6;
        __syncthreads();
#pragma unroll
        for (int it = 0; it < 4; it++) {
            int j = tid + it * 256;
            int rr = j >> 3, c8 = j & 7;
            int idx = (row0 + rr) * 512 + k0 + c8 * 8;
            float iv = inv[head * Nn + row0 + rr];
            uint4 u0 = *(const uint4*)&S0h[idx];
            uint4 u1 = *(const uint4*)&S1h[idx];
            const __half2* h0 = (const __half2*)&u0;
            const __half2* h1 = (const __half2*)&u1;
            uint4 uo;
            __half2* ho = (__half2*)&uo;
#pragma unroll
            for (int e = 0; e < 4; e++) {
                float2 f0 = __half22float2(h0[e]);
                float2 f1 = __half22float2(h1[e]);
                ho[e] = __floats2half2_rn((f0.x + f1.x) * iv, (f0.y + f1.y) * iv);
            }
            *(uint4*)&As[rr * 72 + c8 * 8] = uo;
        }
#pragma unroll
        for (int it = 0; it < 2; it++) {
            int j = tid + it * 256;
            int rr = j >> 3, c8 = j & 7;
            const float* src = &W[(k0 + rr) * 256 + col0 + c8 * 8];
            *(uint4*)&Ws[rr * 72 + c8 * 8] =
                pack8h(*(const float4*)src, *(const float4*)(src + 4));
        }
        __syncthreads();
#pragma unroll
        for (int kk = 0; kk < 4; kk++) {
            uint32_t a[4];
            ldm_x4(a, As + arow * 72 + kk * 16 + acoff);
#pragma unroll
            for (int dtp = 0; dtp < 4; dtp++) {
                uint32_t b[4];
                ldm_x4_trans(b, Ws + (kk * 16 + brow) * 72 + dtp * 16 + bcoff);
                mma_f16(o[2 * dtp],     a[0], a[1], a[2], a[3], b[0], b[1]);
                mma_f16(o[2 * dtp + 1], a[0], a[1], a[2], a[3], b[2], b[3]);
            }
        }
    }

    const int r = row0 + wid * 16 + g;
#pragma unroll
    for (int nt = 0; nt < 8; nt++) {
        int c = col0 + nt * 8 + 2 * q;
        float b0 = bias[c], b1 = bias[c + 1];
        *(float2*)&C[r * 256 + c] = make_float2(o[nt][0] + b0, o[nt][1] + b1);
        *(float2*)&C[(r + 8) * 256 + c] = make_float2(o[nt][2] + b0, o[nt][3] + b1);
    }
}

extern "C" void kernel_launch(void* const* d_in, const int* in_sizes, int n_in,
                              void* d_out, int out_size) {
    Ptrs ptrs;
    for (int i = 0; i < 16; i++) ptrs.p[i] = (const float*)d_in[i];
    float* out = (float*)d_out;

    const int fused_smem = (9216 + 8 * 4608) * 2;   // 90 KB
    cudaFuncSetAttribute(fused_dir_kernel, cudaFuncAttributeMaxDynamicSharedMemorySize,
                         fused_smem);

    {
        dim3 grid(512 / 64, Nn / 128, 4);
        proj_f16_kernel<<<grid, 256>>>(ptrs);
    }
    {
        dim3 grid(Nn / 128, NHEADS, 4);
        fused_dir_kernel<<<grid, 256, fused_smem>>>();
    }
    recip_kernel<<<128, 256>>>();
    {
        dim3 grid(256 / 64, Nn / 128, 2);
        outproj_f16_kernel<<<grid, 256>>>(ptrs, out);
    }
}

// round 13
// speedup vs baseline: 1.1162x; 1.1162x over previous
#include <cuda_runtime.h>
#include <cuda_fp16.h>
#include <math.h>
#include <stdint.h>

#define Nn 4096
#define NHEADS 8
#define SQFC 0.42466090f   // sqrt(SCALE * log2(e))
#define FULLM 0xffffffffu

// fp16 projections (K1/K2 pre-scaled by SQFC)
__device__ __half g_K1H[Nn * 512];
__device__ __half g_K2H[Nn * 512];
__device__ __half g_V1H[Nn * 512];
__device__ __half g_V2H[Nn * 512];
// fp16 partial attention outputs: slab z = dir*2 + ks
__device__ __half g_Oph[4][Nn * 512];
// per-slab row-sum partials (direct store, no atomics/zeroing)
__device__ float g_sumP[4][NHEADS * Nn];
__device__ float g_rsum[NHEADS * Nn];   // holds 1/rowsum after recip
__device__ float g_csum[NHEADS * Nn];   // holds 1/colsum after recip

struct Ptrs {
    const float* p[16];
};

__device__ __forceinline__ void mma_f16(float c[4],
                                        uint32_t a0, uint32_t a1, uint32_t a2, uint32_t a3,
                                        uint32_t b0, uint32_t b1) {
    asm volatile(
        "mma.sync.aligned.m16n8k16.row.col.f32.f16.f16.f32 "
        "{%0,%1,%2,%3}, {%4,%5,%6,%7}, {%8,%9}, {%0,%1,%2,%3};\n"
        : "+f"(c[0]), "+f"(c[1]), "+f"(c[2]), "+f"(c[3])
        : "r"(a0), "r"(a1), "r"(a2), "r"(a3), "r"(b0), "r"(b1));
}

// f16-accumulator variant: D/C are 2 packed f16x2 regs
__device__ __forceinline__ void mma_f16h(uint32_t c[2],
                                         uint32_t a0, uint32_t a1, uint32_t a2, uint32_t a3,
                                         uint32_t b0, uint32_t b1) {
    asm volatile(
        "mma.sync.aligned.m16n8k16.row.col.f16.f16.f16.f16 "
        "{%0,%1}, {%2,%3,%4,%5}, {%6,%7}, {%0,%1};\n"
        : "+r"(c[0]), "+r"(c[1])
        : "r"(a0), "r"(a1), "r"(a2), "r"(a3), "r"(b0), "r"(b1));
}

__device__ __forceinline__ void ldm_x4(uint32_t r[4], const void* ptr) {
    uint32_t addr = (uint32_t)__cvta_generic_to_shared(ptr);
    asm volatile("ldmatrix.sync.aligned.m8n8.x4.shared.b16 {%0,%1,%2,%3}, [%4];"
                 : "=r"(r[0]), "=r"(r[1]), "=r"(r[2]), "=r"(r[3]) : "r"(addr));
}

__device__ __forceinline__ void ldm_x4_trans(uint32_t r[4], const void* ptr) {
    uint32_t addr = (uint32_t)__cvta_generic_to_shared(ptr);
    asm volatile("ldmatrix.sync.aligned.m8n8.x4.trans.shared.b16 {%0,%1,%2,%3}, [%4];"
                 : "=r"(r[0]), "=r"(r[1]), "=r"(r[2]), "=r"(r[3]) : "r"(addr));
}

__device__ __forceinline__ void cp16(void* smem_dst, const void* gsrc) {
    uint32_t d = (uint32_t)__cvta_generic_to_shared(smem_dst);
    asm volatile("cp.async.cg.shared.global [%0], [%1], 16;" :: "r"(d), "l"(gsrc));
}

__device__ __forceinline__ uint32_t ex2p(uint32_t h2) {
    uint32_t r;
    asm("ex2.approx.f16x2 %0, %1;" : "=r"(r) : "r"(h2));
    return r;
}

__device__ __forceinline__ uint4 pack8h(float4 v0, float4 v1) {
    uint4 u;
    __half2* h = (__half2*)&u;
    h[0] = __floats2half2_rn(v0.x, v0.y);
    h[1] = __floats2half2_rn(v0.z, v0.w);
    h[2] = __floats2half2_rn(v1.x, v1.y);
    h[3] = __floats2half2_rn(v1.z, v1.w);
    return u;
}

// ---------------------------------------------------------------------------
// merge row-sum partials -> reciprocals
// ---------------------------------------------------------------------------
__global__ void recip_kernel() {
    int i = blockIdx.x * 256 + threadIdx.x;   // 32768
    g_rsum[i] = 1.0f / (g_sumP[0][i] + g_sumP[1][i]);
    g_csum[i] = 1.0f / (g_sumP[2][i] + g_sumP[3][i]);
}

// ---------------------------------------------------------------------------
// Projection (fp16 mma): C = A @ W + bias -> fp16; K1/K2 scaled by SQFC.
// grid (8, 32, 4), 256 thr.
// ---------------------------------------------------------------------------
__global__ __launch_bounds__(256) void proj_f16_kernel(Ptrs in) {
    const float *A, *W, *bias;
    __half* C;
    float sc;
    switch (blockIdx.z) {
        case 0: A = in.p[0]; W = in.p[4];  bias = in.p[5];  C = g_K1H; sc = SQFC; break;
        case 1: A = in.p[1]; W = in.p[6];  bias = in.p[7];  C = g_V1H; sc = 1.0f; break;
        case 2: A = in.p[2]; W = in.p[8];  bias = in.p[9];  C = g_K2H; sc = SQFC; break;
        default:A = in.p[3]; W = in.p[10]; bias = in.p[11]; C = g_V2H; sc = 1.0f; break;
    }
    __shared__ __half As[128 * 72];
    __shared__ __half Ws[64 * 72];

    const int tid = threadIdx.x;
    const int lane = tid & 31, wid = tid >> 5;
    const int q = lane & 3, g = lane >> 2;
    const int row0 = blockIdx.y * 128;
    const int col0 = blockIdx.x * 64;
    const int brow = ((lane >> 3) & 1) * 8 + (lane & 7);
    const int bcoff = (lane >> 4) * 8;
    const int arow = wid * 16 + (lane & 7) + ((lane >> 3) & 1) * 8;
    const int acoff = (lane >> 4) * 8;

    float o[8][4];
#pragma unroll
    for (int nt = 0; nt < 8; nt++)
#pragma unroll
        for (int j = 0; j < 4; j++) o[nt][j] = 0.f;

    for (int k0 = 0; k0 < 256; k0 += 64) {
        __syncthreads();
#pragma unroll
        for (int it = 0; it < 4; it++) {
            int j = tid + it * 256;
            int rr = j >> 3, c8 = j & 7;
            const float* src = &A[(row0 + rr) * 256 + k0 + c8 * 8];
            *(uint4*)&As[rr * 72 + c8 * 8] =
                pack8h(*(const float4*)src, *(const float4*)(src + 4));
        }
#pragma unroll
        for (int it = 0; it < 2; it++) {
            int j = tid + it * 256;
            int rr = j >> 3, c8 = j & 7;
            const float* src = &W[(k0 + rr) * 512 + col0 + c8 * 8];
            *(uint4*)&Ws[rr * 72 + c8 * 8] =
                pack8h(*(const float4*)src, *(const float4*)(src + 4));
        }
        __syncthreads();
#pragma unroll
        for (int kk = 0; kk < 4; kk++) {
            uint32_t a[4];
            ldm_x4(a, As + arow * 72 + kk * 16 + acoff);
#pragma unroll
            for (int dtp = 0; dtp < 4; dtp++) {
                uint32_t b[4];
                ldm_x4_trans(b, Ws + (kk * 16 + brow) * 72 + dtp * 16 + bcoff);
                mma_f16(o[2 * dtp],     a[0], a[1], a[2], a[3], b[0], b[1]);
                mma_f16(o[2 * dtp + 1], a[0], a[1], a[2], a[3], b[2], b[3]);
            }
        }
    }

    const int r = row0 + wid * 16 + g;
#pragma unroll
    for (int nt = 0; nt < 8; nt++) {
        int c = col0 + nt * 8 + 2 * q;
        float b0 = bias[c], b1 = bias[c + 1];
        __half2 h0 = __floats2half2_rn((o[nt][0] + b0) * sc, (o[nt][1] + b1) * sc);
        __half2 h1 = __floats2half2_rn((o[nt][2] + b0) * sc, (o[nt][3] + b1) * sc);
        *(uint32_t*)&C[r * 512 + c] = *(uint32_t*)&h0;
        *(uint32_t*)&C[(r + 8) * 512 + c] = *(uint32_t*)&h1;
    }
}

// ---------------------------------------------------------------------------
// Fused dual attention: P stays in REGISTERS (S C-fragment == PV A-fragment).
// No P smem, no STS/ldsm for P, no syncwarp. f16-accum S, f32-accum PV.
// grid (32, 8, 4): z = dir*2 + ks. 4-stage cp.async K/V pipeline, 72KB smem.
// ---------------------------------------------------------------------------
__global__ __launch_bounds__(256, 2) void fused_dir_kernel() {
    extern __shared__ __half sm[];
    __half* Kb = sm;                 // 4 x [64][72]; also Q staging (slots 0-1) at init
    __half* Vb = sm + 4 * 4608;      // 4 x [64][72]

    const int n0 = blockIdx.x * 128;
    const int head = blockIdx.y;
    const int hc = head * 64;
    const int z = blockIdx.z;
    const int dir = z >> 1;
    const int ks = z & 1;

    const __half* Qg = dir ? g_K2H : g_K1H;
    const __half* Kg = dir ? g_K1H : g_K2H;
    const __half* Vg = dir ? g_V1H : g_V2H;

    const int tid = threadIdx.x;
    const int lane = tid & 31, wid = tid >> 5;
    const int q = lane & 3, g = lane >> 2;
    const int arow_lm = wid * 16 + (lane & 7) + ((lane >> 3) & 1) * 8;
    const int acoff = (lane >> 4) * 8;
    const int brow2 = ((lane >> 3) & 1) * 8 + (lane & 7);
    const int bcoff = (lane >> 4) * 8;
    const int arow = wid * 16 + g;

    // ---- stage Q in Kb slots 0-1, build A-fragments ----
#pragma unroll
    for (int it = 0; it < 4; it++) {
        int j = tid + it * 256;
        int rr = j >> 3, c8 = j & 7;
        cp16(Kb + rr * 72 + c8 * 8, Qg + (n0 + rr) * 512 + hc + c8 * 8);
    }
    asm volatile("cp.async.commit_group;" ::: "memory");
    asm volatile("cp.async.wait_group 0;" ::: "memory");
    __syncthreads();

    uint32_t af[4][4];
#pragma unroll
    for (int kk = 0; kk < 4; kk++)
        ldm_x4(af[kk], Kb + arow_lm * 72 + kk * 16 + acoff);
    __syncthreads();   // Q staging free

    auto issue = [&](int s) {
        const int m0 = (ks * 32 + s) * 64;
        __half* Kd = Kb + (s & 3) * 4608;
        __half* Vd = Vb + (s & 3) * 4608;
#pragma unroll
        for (int it = 0; it < 2; it++) {
            int j = tid + it * 256;
            int rr = j >> 3, c8 = j & 7;
            cp16(Kd + rr * 72 + c8 * 8, Kg + (m0 + rr) * 512 + hc + c8 * 8);
            cp16(Vd + rr * 72 + c8 * 8, Vg + (m0 + rr) * 512 + hc + c8 * 8);
        }
        asm volatile("cp.async.commit_group;" ::: "memory");
    };

    issue(0);
    issue(1);
    issue(2);

    float o[8][4];
#pragma unroll
    for (int dt = 0; dt < 8; dt++)
#pragma unroll
        for (int j = 0; j < 4; j++) o[dt][j] = 0.f;
    float rloc0 = 0.f, rloc1 = 0.f;

    for (int i = 0; i < 32; i++) {
        if (i < 30)       asm volatile("cp.async.wait_group 2;" ::: "memory");
        else if (i == 30) asm volatile("cp.async.wait_group 1;" ::: "memory");
        else              asm volatile("cp.async.wait_group 0;" ::: "memory");
        __syncthreads();   // stage i visible; slot (i-1)&3 free

        if (i + 3 < 32) issue(i + 3);

        const __half* Kc = Kb + (i & 3) * 4608;
        const __half* Vc = Vb + (i & 3) * 4608;

        // ---- S (f16 accum) + exp: P fragments stay in registers ----
        // p[kc][0..3] are exactly the PV A-fragments (a0,a1,a2,a3) for k-chunk kc.
        uint32_t p[4][4];
#pragma unroll
        for (int nt2 = 0; nt2 < 4; nt2++) {
            uint32_t s0[2] = {0u, 0u};
            uint32_t s1[2] = {0u, 0u};
#pragma unroll
            for (int kk = 0; kk < 4; kk++) {
                uint32_t bq[4];
                ldm_x4(bq, Kc + (nt2 * 16 + brow2) * 72 + kk * 16 + bcoff);
                mma_f16h(s0, af[kk][0], af[kk][1], af[kk][2], af[kk][3], bq[0], bq[2]);
                mma_f16h(s1, af[kk][0], af[kk][1], af[kk][2], af[kk][3], bq[1], bq[3]);
            }
            p[nt2][0] = ex2p(s0[0]);   // P[g][nt2*16+2q..+1]      -> a0
            p[nt2][1] = ex2p(s0[1]);   // P[g+8][nt2*16+2q..+1]    -> a1
            p[nt2][2] = ex2p(s1[0]);   // P[g][nt2*16+8+2q..+1]    -> a2
            p[nt2][3] = ex2p(s1[1]);   // P[g+8][nt2*16+8+2q..+1]  -> a3
            __half2 hA = __hadd2(*(__half2*)&p[nt2][0], *(__half2*)&p[nt2][2]);  // row g
            __half2 hB = __hadd2(*(__half2*)&p[nt2][1], *(__half2*)&p[nt2][3]);  // row g+8
            float2 fA = __half22float2(hA);
            float2 fB = __half22float2(hB);
            rloc0 += fA.x + fA.y;
            rloc1 += fB.x + fB.y;
        }

        // ---- o += P(regs) @ V(64x64), f32 accum ----
#pragma unroll
        for (int kc = 0; kc < 4; kc++) {
#pragma unroll
            for (int dtp = 0; dtp < 4; dtp++) {
                uint32_t b[4];
                ldm_x4_trans(b, Vc + (kc * 16 + brow2) * 72 + dtp * 16 + bcoff);
                mma_f16(o[2 * dtp],     p[kc][0], p[kc][1], p[kc][2], p[kc][3], b[0], b[1]);
                mma_f16(o[2 * dtp + 1], p[kc][0], p[kc][1], p[kc][2], p[kc][3], b[2], b[3]);
            }
        }
    }

    // ---- flush partial o (fp16 direct store) + row-sum partials ----
    {
        const int rN = n0 + arow;
        __half* Og = g_Oph[z] + rN * 512 + hc;
#pragma unroll
        for (int dt = 0; dt < 8; dt++) {
            __half2 h0 = __floats2half2_rn(o[dt][0], o[dt][1]);
            __half2 h1 = __floats2half2_rn(o[dt][2], o[dt][3]);
            *(uint32_t*)&Og[dt * 8 + 2 * q] = *(uint32_t*)&h0;
            *(uint32_t*)&Og[8 * 512 + dt * 8 + 2 * q] = *(uint32_t*)&h1;
        }
    }
    rloc0 += __shfl_xor_sync(FULLM, rloc0, 1);
    rloc0 += __shfl_xor_sync(FULLM, rloc0, 2);
    rloc1 += __shfl_xor_sync(FULLM, rloc1, 1);
    rloc1 += __shfl_xor_sync(FULLM, rloc1, 2);
    if (q == 0) {
        g_sumP[z][head * Nn + n0 + arow] = rloc0;
        g_sumP[z][head * Nn + n0 + arow + 8] = rloc1;
    }
}

// ---------------------------------------------------------------------------
// Output GEMM (fp16 mma): out = ((S0+S1) * inv) @ Wo + bias. grid (4, 32, 2).
// ---------------------------------------------------------------------------
__global__ __launch_bounds__(256) void outproj_f16_kernel(Ptrs in, float* out) {
    const __half *S0h, *S1h;
    const float *inv, *W, *bias;
    float* C;
    if (blockIdx.z == 0) {
        S0h = g_Oph[2]; S1h = g_Oph[3]; inv = g_csum;
        W = in.p[12]; bias = in.p[13]; C = out;
    } else {
        S0h = g_Oph[0]; S1h = g_Oph[1]; inv = g_rsum;
        W = in.p[14]; bias = in.p[15]; C = out + Nn * 256;
    }
    __shared__ __half As[128 * 72];
    __shared__ __half Ws[64 * 72];

    const int tid = threadIdx.x;
    const int lane = tid & 31, wid = tid >> 5;
    const int q = lane & 3, g = lane >> 2;
    const int row0 = blockIdx.y * 128;
    const int col0 = blockIdx.x * 64;
    const int brow = ((lane >> 3) & 1) * 8 + (lane & 7);
    const int bcoff = (lane >> 4) * 8;
    const int arow = wid * 16 + (lane & 7) + ((lane >> 3) & 1) * 8;
    const int acoff = (lane >> 4) * 8;

    float o[8][4];
#pragma unroll
    for (int nt = 0; nt < 8; nt++)
#pragma unroll
        for (int j = 0; j < 4; j++) o[nt][j] = 0.f;

    for (int k0 = 0; k0 < 512; k0 += 64) {
        const int head = k0 >> 6;
        __syncthreads();
#pragma unroll
        for (int it = 0; it < 4; it++) {
            int j = tid + it * 256;
            int rr = j >> 3, c8 = j & 7;
            int idx = (row0 + rr) * 512 + k0 + c8 * 8;
            float iv = inv[head * Nn + row0 + rr];
            uint4 u0 = *(const uint4*)&S0h[idx];
            uint4 u1 = *(const uint4*)&S1h[idx];
            const __half2* h0 = (const __half2*)&u0;
            const __half2* h1 = (const __half2*)&u1;
            uint4 uo;
            __half2* ho = (__half2*)&uo;
#pragma unroll
            for (int e = 0; e < 4; e++) {
                float2 f0 = __half22float2(h0[e]);
                float2 f1 = __half22float2(h1[e]);
                ho[e] = __floats2half2_rn((f0.x + f1.x) * iv, (f0.y + f1.y) * iv);
            }
            *(uint4*)&As[rr * 72 + c8 * 8] = uo;
        }
#pragma unroll
        for (int it = 0; it < 2; it++) {
            int j = tid + it * 256;
            int rr = j >> 3, c8 = j & 7;
            const float* src = &W[(k0 + rr) * 256 + col0 + c8 * 8];
            *(uint4*)&Ws[rr * 72 + c8 * 8] =
                pack8h(*(const float4*)src, *(const float4*)(src + 4));
        }
        __syncthreads();
#pragma unroll
        for (int kk = 0; kk < 4; kk++) {
            uint32_t a[4];
            ldm_x4(a, As + arow * 72 + kk * 16 + acoff);
#pragma unroll
            for (int dtp = 0; dtp < 4; dtp++) {
                uint32_t b[4];
                ldm_x4_trans(b, Ws + (kk * 16 + brow) * 72 + dtp * 16 + bcoff);
                mma_f16(o[2 * dtp],     a[0], a[1], a[2], a[3], b[0], b[1]);
                mma_f16(o[2 * dtp + 1], a[0], a[1], a[2], a[3], b[2], b[3]);
            }
        }
    }

    const int r = row0 + wid * 16 + g;
#pragma unroll
    for (int nt = 0; nt < 8; nt++) {
        int c = col0 + nt * 8 + 2 * q;
        float b0 = bias[c], b1 = bias[c + 1];
        *(float2*)&C[r * 256 + c] = make_float2(o[nt][0] + b0, o[nt][1] + b1);
        *(float2*)&C[(r + 8) * 256 + c] = make_float2(o[nt][2] + b0, o[nt][3] + b1);
    }
}

extern "C" void kernel_launch(void* const* d_in, const int* in_sizes, int n_in,
                              void* d_out, int out_size) {
    Ptrs ptrs;
    for (int i = 0; i < 16; i++) ptrs.p[i] = (const float*)d_in[i];
    float* out = (float*)d_out;

    const int fused_smem = 8 * 4608 * 2;   // 72 KB
    cudaFuncSetAttribute(fused_dir_kernel, cudaFuncAttributeMaxDynamicSharedMemorySize,
                         fused_smem);

    {
        dim3 grid(512 / 64, Nn / 128, 4);
        proj_f16_kernel<<<grid, 256>>>(ptrs);
    }
    {
        dim3 grid(Nn / 128, NHEADS, 4);
        fused_dir_kernel<<<grid, 256, fused_smem>>>();
    }
    recip_kernel<<<128, 256>>>();
    {
        dim3 grid(256 / 64, Nn / 128, 2);
        outproj_f16_kernel<<<grid, 256>>>(ptrs, out);
    }
}

// round 14
// speedup vs baseline: 1.1495x; 1.0298x over previous
#include <cuda_runtime.h>
#include <cuda_fp16.h>
#include <math.h>
#include <stdint.h>

#define Nn 4096
#define NHEADS 8
#define SQFC 0.42466090f   // sqrt(SCALE * log2(e))
#define FULLM 0xffffffffu

// fp16 projections (K1/K2 pre-scaled by SQFC)
__device__ __half g_K1H[Nn * 512];
__device__ __half g_K2H[Nn * 512];
__device__ __half g_V1H[Nn * 512];
__device__ __half g_V2H[Nn * 512];
// fp16 partial attention outputs: slab z = dir*2 + ks
__device__ __half g_Oph[4][Nn * 512];
// per-slab row-sum partials (direct store, no atomics/zeroing)
__device__ float g_sumP[4][NHEADS * Nn];
__device__ float g_rsum[NHEADS * Nn];   // holds 1/rowsum after recip
__device__ float g_csum[NHEADS * Nn];   // holds 1/colsum after recip

struct Ptrs {
    const float* p[16];
};

__device__ __forceinline__ void mma_f16(float c[4],
                                        uint32_t a0, uint32_t a1, uint32_t a2, uint32_t a3,
                                        uint32_t b0, uint32_t b1) {
    asm volatile(
        "mma.sync.aligned.m16n8k16.row.col.f32.f16.f16.f32 "
        "{%0,%1,%2,%3}, {%4,%5,%6,%7}, {%8,%9}, {%0,%1,%2,%3};\n"
        : "+f"(c[0]), "+f"(c[1]), "+f"(c[2]), "+f"(c[3])
        : "r"(a0), "r"(a1), "r"(a2), "r"(a3), "r"(b0), "r"(b1));
}

// f16-accumulator variant: D/C are 2 packed f16x2 regs
__device__ __forceinline__ void mma_f16h(uint32_t c[2],
                                         uint32_t a0, uint32_t a1, uint32_t a2, uint32_t a3,
                                         uint32_t b0, uint32_t b1) {
    asm volatile(
        "mma.sync.aligned.m16n8k16.row.col.f16.f16.f16.f16 "
        "{%0,%1}, {%2,%3,%4,%5}, {%6,%7}, {%0,%1};\n"
        : "+r"(c[0]), "+r"(c[1])
        : "r"(a0), "r"(a1), "r"(a2), "r"(a3), "r"(b0), "r"(b1));
}

__device__ __forceinline__ void ldm_x4(uint32_t r[4], const void* ptr) {
    uint32_t addr = (uint32_t)__cvta_generic_to_shared(ptr);
    asm volatile("ldmatrix.sync.aligned.m8n8.x4.shared.b16 {%0,%1,%2,%3}, [%4];"
                 : "=r"(r[0]), "=r"(r[1]), "=r"(r[2]), "=r"(r[3]) : "r"(addr));
}

__device__ __forceinline__ void ldm_x4_trans(uint32_t r[4], const void* ptr) {
    uint32_t addr = (uint32_t)__cvta_generic_to_shared(ptr);
    asm volatile("ldmatrix.sync.aligned.m8n8.x4.trans.shared.b16 {%0,%1,%2,%3}, [%4];"
                 : "=r"(r[0]), "=r"(r[1]), "=r"(r[2]), "=r"(r[3]) : "r"(addr));
}

__device__ __forceinline__ void cp16(void* smem_dst, const void* gsrc) {
    uint32_t d = (uint32_t)__cvta_generic_to_shared(smem_dst);
    asm volatile("cp.async.cg.shared.global [%0], [%1], 16;" :: "r"(d), "l"(gsrc));
}

__device__ __forceinline__ uint32_t ex2p(uint32_t h2) {
    uint32_t r;
    asm("ex2.approx.f16x2 %0, %1;" : "=r"(r) : "r"(h2));
    return r;
}

__device__ __forceinline__ uint4 pack8h(float4 v0, float4 v1) {
    uint4 u;
    __half2* h = (__half2*)&u;
    h[0] = __floats2half2_rn(v0.x, v0.y);
    h[1] = __floats2half2_rn(v0.z, v0.w);
    h[2] = __floats2half2_rn(v1.x, v1.y);
    h[3] = __floats2half2_rn(v1.z, v1.w);
    return u;
}

// ---------------------------------------------------------------------------
__global__ void recip_kernel() {
    int i = blockIdx.x * 256 + threadIdx.x;   // 32768
    g_rsum[i] = 1.0f / (g_sumP[0][i] + g_sumP[1][i]);
    g_csum[i] = 1.0f / (g_sumP[2][i] + g_sumP[3][i]);
}

// ---------------------------------------------------------------------------
// Projection (fp16 mma): C = A @ W + bias -> fp16; K1/K2 scaled by SQFC.
// grid (8, 32, 4), 256 thr.
// ---------------------------------------------------------------------------
__global__ __launch_bounds__(256) void proj_f16_kernel(Ptrs in) {
    const float *A, *W, *bias;
    __half* C;
    float sc;
    switch (blockIdx.z) {
        case 0: A = in.p[0]; W = in.p[4];  bias = in.p[5];  C = g_K1H; sc = SQFC; break;
        case 1: A = in.p[1]; W = in.p[6];  bias = in.p[7];  C = g_V1H; sc = 1.0f; break;
        case 2: A = in.p[2]; W = in.p[8];  bias = in.p[9];  C = g_K2H; sc = SQFC; break;
        default:A = in.p[3]; W = in.p[10]; bias = in.p[11]; C = g_V2H; sc = 1.0f; break;
    }
    __shared__ __half As[128 * 72];
    __shared__ __half Ws[64 * 72];

    const int tid = threadIdx.x;
    const int lane = tid & 31, wid = tid >> 5;
    const int q = lane & 3, g = lane >> 2;
    const int row0 = blockIdx.y * 128;
    const int col0 = blockIdx.x * 64;
    const int brow = ((lane >> 3) & 1) * 8 + (lane & 7);
    const int bcoff = (lane >> 4) * 8;
    const int arow = wid * 16 + (lane & 7) + ((lane >> 3) & 1) * 8;
    const int acoff = (lane >> 4) * 8;

    float o[8][4];
#pragma unroll
    for (int nt = 0; nt < 8; nt++)
#pragma unroll
        for (int j = 0; j < 4; j++) o[nt][j] = 0.f;

    for (int k0 = 0; k0 < 256; k0 += 64) {
        __syncthreads();
#pragma unroll
        for (int it = 0; it < 4; it++) {
            int j = tid + it * 256;
            int rr = j >> 3, c8 = j & 7;
            const float* src = &A[(row0 + rr) * 256 + k0 + c8 * 8];
            *(uint4*)&As[rr * 72 + c8 * 8] =
                pack8h(*(const float4*)src, *(const float4*)(src + 4));
        }
#pragma unroll
        for (int it = 0; it < 2; it++) {
            int j = tid + it * 256;
            int rr = j >> 3, c8 = j & 7;
            const float* src = &W[(k0 + rr) * 512 + col0 + c8 * 8];
            *(uint4*)&Ws[rr * 72 + c8 * 8] =
                pack8h(*(const float4*)src, *(const float4*)(src + 4));
        }
        __syncthreads();
#pragma unroll
        for (int kk = 0; kk < 4; kk++) {
            uint32_t a[4];
            ldm_x4(a, As + arow * 72 + kk * 16 + acoff);
#pragma unroll
            for (int dtp = 0; dtp < 4; dtp++) {
                uint32_t b[4];
                ldm_x4_trans(b, Ws + (kk * 16 + brow) * 72 + dtp * 16 + bcoff);
                mma_f16(o[2 * dtp],     a[0], a[1], a[2], a[3], b[0], b[1]);
                mma_f16(o[2 * dtp + 1], a[0], a[1], a[2], a[3], b[2], b[3]);
            }
        }
    }

    const int r = row0 + wid * 16 + g;
#pragma unroll
    for (int nt = 0; nt < 8; nt++) {
        int c = col0 + nt * 8 + 2 * q;
        float b0 = bias[c], b1 = bias[c + 1];
        __half2 h0 = __floats2half2_rn((o[nt][0] + b0) * sc, (o[nt][1] + b1) * sc);
        __half2 h1 = __floats2half2_rn((o[nt][2] + b0) * sc, (o[nt][3] + b1) * sc);
        *(uint32_t*)&C[r * 512 + c] = *(uint32_t*)&h0;
        *(uint32_t*)&C[(r + 8) * 512 + c] = *(uint32_t*)&h1;
    }
}

// ---------------------------------------------------------------------------
// Fused dual attention: register-resident P, 6-slot cp.async ring,
// TWO 64-key tiles per __syncthreads (16 barriers total).
// grid (32, 8, 4): z = dir*2 + ks. 108KB smem, occ 2.
// ---------------------------------------------------------------------------
#define SLOT 4608   // halves per tile slot (64 rows x 72)

__global__ __launch_bounds__(256, 2) void fused_dir_kernel() {
    extern __shared__ __half sm[];
    __half* Kb = sm;                 // 6 slots; slots 0-1 double as Q staging at init
    __half* Vb = sm + 6 * SLOT;      // 6 slots

    const int n0 = blockIdx.x * 128;
    const int head = blockIdx.y;
    const int hc = head * 64;
    const int z = blockIdx.z;
    const int dir = z >> 1;
    const int ks = z & 1;

    const __half* Qg = dir ? g_K2H : g_K1H;
    const __half* Kg = dir ? g_K1H : g_K2H;
    const __half* Vg = dir ? g_V1H : g_V2H;

    const int tid = threadIdx.x;
    const int lane = tid & 31, wid = tid >> 5;
    const int q = lane & 3, g = lane >> 2;
    const int arow_lm = wid * 16 + (lane & 7) + ((lane >> 3) & 1) * 8;
    const int acoff = (lane >> 4) * 8;
    const int brow2 = ((lane >> 3) & 1) * 8 + (lane & 7);
    const int bcoff = (lane >> 4) * 8;
    const int arow = wid * 16 + g;

    // ---- stage Q in Kb slots 0-1, build A-fragments ----
#pragma unroll
    for (int it = 0; it < 4; it++) {
        int j = tid + it * 256;
        int rr = j >> 3, c8 = j & 7;
        cp16(Kb + rr * 72 + c8 * 8, Qg + (n0 + rr) * 512 + hc + c8 * 8);
    }
    asm volatile("cp.async.commit_group;" ::: "memory");
    asm volatile("cp.async.wait_group 0;" ::: "memory");
    __syncthreads();

    uint32_t af[4][4];
#pragma unroll
    for (int kk = 0; kk < 4; kk++)
        ldm_x4(af[kk], Kb + arow_lm * 72 + kk * 16 + acoff);
    __syncthreads();   // Q staging free

    // issue one group = two consecutive stages (2g, 2g+1)
    auto issue2 = [&](int grp) {
#pragma unroll
        for (int e = 0; e < 2; e++) {
            const int s = 2 * grp + e;
            const int m0 = (ks * 32 + s) * 64;
            __half* Kd = Kb + (s % 6) * SLOT;
            __half* Vd = Vb + (s % 6) * SLOT;
#pragma unroll
            for (int it = 0; it < 2; it++) {
                int j = tid + it * 256;
                int rr = j >> 3, c8 = j & 7;
                cp16(Kd + rr * 72 + c8 * 8, Kg + (m0 + rr) * 512 + hc + c8 * 8);
                cp16(Vd + rr * 72 + c8 * 8, Vg + (m0 + rr) * 512 + hc + c8 * 8);
            }
        }
        asm volatile("cp.async.commit_group;" ::: "memory");
    };

    issue2(0);
    issue2(1);

    float o[8][4];
#pragma unroll
    for (int dt = 0; dt < 8; dt++)
#pragma unroll
        for (int j = 0; j < 4; j++) o[dt][j] = 0.f;
    float rloc0 = 0.f, rloc1 = 0.f;

    // process one 64-key tile from the given slot
    auto process = [&](int slot) {
        const __half* Kc = Kb + slot * SLOT;
        const __half* Vc = Vb + slot * SLOT;

        uint32_t p[4][4];
        __half2 hsA = __floats2half2_rn(0.f, 0.f);
        __half2 hsB = hsA;
#pragma unroll
        for (int nt2 = 0; nt2 < 4; nt2++) {
            uint32_t s0[2] = {0u, 0u};
            uint32_t s1[2] = {0u, 0u};
#pragma unroll
            for (int kk = 0; kk < 4; kk++) {
                uint32_t bq[4];
                ldm_x4(bq, Kc + (nt2 * 16 + brow2) * 72 + kk * 16 + bcoff);
                mma_f16h(s0, af[kk][0], af[kk][1], af[kk][2], af[kk][3], bq[0], bq[2]);
                mma_f16h(s1, af[kk][0], af[kk][1], af[kk][2], af[kk][3], bq[1], bq[3]);
            }
            p[nt2][0] = ex2p(s0[0]);
            p[nt2][1] = ex2p(s0[1]);
            p[nt2][2] = ex2p(s1[0]);
            p[nt2][3] = ex2p(s1[1]);
            hsA = __hadd2(hsA, __hadd2(*(__half2*)&p[nt2][0], *(__half2*)&p[nt2][2]));
            hsB = __hadd2(hsB, __hadd2(*(__half2*)&p[nt2][1], *(__half2*)&p[nt2][3]));
        }
        float2 fA = __half22float2(hsA);
        float2 fB = __half22float2(hsB);
        rloc0 += fA.x + fA.y;
        rloc1 += fB.x + fB.y;

#pragma unroll
        for (int kc = 0; kc < 4; kc++) {
#pragma unroll
            for (int dtp = 0; dtp < 4; dtp++) {
                uint32_t b[4];
                ldm_x4_trans(b, Vc + (kc * 16 + brow2) * 72 + dtp * 16 + bcoff);
                mma_f16(o[2 * dtp],     p[kc][0], p[kc][1], p[kc][2], p[kc][3], b[0], b[1]);
                mma_f16(o[2 * dtp + 1], p[kc][0], p[kc][1], p[kc][2], p[kc][3], b[2], b[3]);
            }
        }
    };

    for (int grp = 0; grp < 16; grp++) {
        if (grp == 15) asm volatile("cp.async.wait_group 0;" ::: "memory");
        else           asm volatile("cp.async.wait_group 1;" ::: "memory");
        __syncthreads();   // group grp visible; group grp-1 slots free everywhere

        if (grp + 2 < 16) issue2(grp + 2);   // targets slots of group grp-1

        process((2 * grp) % 6);
        process((2 * grp + 1) % 6);
    }

    // ---- flush partial o (fp16 direct store) + row-sum partials ----
    {
        const int rN = n0 + arow;
        __half* Og = g_Oph[z] + rN * 512 + hc;
#pragma unroll
        for (int dt = 0; dt < 8; dt++) {
            __half2 h0 = __floats2half2_rn(o[dt][0], o[dt][1]);
            __half2 h1 = __floats2half2_rn(o[dt][2], o[dt][3]);
            *(uint32_t*)&Og[dt * 8 + 2 * q] = *(uint32_t*)&h0;
            *(uint32_t*)&Og[8 * 512 + dt * 8 + 2 * q] = *(uint32_t*)&h1;
        }
    }
    rloc0 += __shfl_xor_sync(FULLM, rloc0, 1);
    rloc0 += __shfl_xor_sync(FULLM, rloc0, 2);
    rloc1 += __shfl_xor_sync(FULLM, rloc1, 1);
    rloc1 += __shfl_xor_sync(FULLM, rloc1, 2);
    if (q == 0) {
        g_sumP[z][head * Nn + n0 + arow] = rloc0;
        g_sumP[z][head * Nn + n0 + arow + 8] = rloc1;
    }
}

// ---------------------------------------------------------------------------
// Output GEMM (fp16 mma): out = ((S0+S1) * inv) @ Wo + bias.
// BM=64: grid (4, 64, 2) = 512 CTAs; warps 4(row) x 2(col), warp tile 16x32.
// ---------------------------------------------------------------------------
__global__ __launch_bounds__(256) void outproj_f16_kernel(Ptrs in, float* out) {
    const __half *S0h, *S1h;
    const float *inv, *W, *bias;
    float* C;
    if (blockIdx.z == 0) {
        S0h = g_Oph[2]; S1h = g_Oph[3]; inv = g_csum;
        W = in.p[12]; bias = in.p[13]; C = out;
    } else {
        S0h = g_Oph[0]; S1h = g_Oph[1]; inv = g_rsum;
        W = in.p[14]; bias = in.p[15]; C = out + Nn * 256;
    }
    __shared__ __half As[64 * 72];
    __shared__ __half Ws[64 * 72];

    const int tid = threadIdx.x;
    const int lane = tid & 31, wid = tid >> 5;
    const int q = lane & 3, g = lane >> 2;
    const int wr = wid & 3, wc = wid >> 2;
    const int row0 = blockIdx.y * 64;
    const int col0 = blockIdx.x * 64;
    const int brow = ((lane >> 3) & 1) * 8 + (lane & 7);
    const int bcoff = (lane >> 4) * 8;
    const int arow = wr * 16 + (lane & 7) + ((lane >> 3) & 1) * 8;
    const int acoff = (lane >> 4) * 8;

    float o[4][4];
#pragma unroll
    for (int nt = 0; nt < 4; nt++)
#pragma unroll
        for (int j = 0; j < 4; j++) o[nt][j] = 0.f;

    for (int k0 = 0; k0 < 512; k0 += 64) {
        const int head = k0 >> 6;
        __syncthreads();
#pragma unroll
        for (int it = 0; it < 2; it++) {
            int j = tid + it * 256;
            int rr = j >> 3, c8 = j & 7;
            int idx = (row0 + rr) * 512 + k0 + c8 * 8;
            float iv = inv[head * Nn + row0 + rr];
            uint4 u0 = *(const uint4*)&S0h[idx];
            uint4 u1 = *(const uint4*)&S1h[idx];
            const __half2* h0 = (const __half2*)&u0;
            const __half2* h1 = (const __half2*)&u1;
            uint4 uo;
            __half2* ho = (__half2*)&uo;
#pragma unroll
            for (int e = 0; e < 4; e++) {
                float2 f0 = __half22float2(h0[e]);
                float2 f1 = __half22float2(h1[e]);
                ho[e] = __floats2half2_rn((f0.x + f1.x) * iv, (f0.y + f1.y) * iv);
            }
            *(uint4*)&As[rr * 72 + c8 * 8] = uo;
        }
#pragma unroll
        for (int it = 0; it < 2; it++) {
            int j = tid + it * 256;
            int rr = j >> 3, c8 = j & 7;
            const float* src = &W[(k0 + rr) * 256 + col0 + c8 * 8];
            *(uint4*)&Ws[rr * 72 + c8 * 8] =
                pack8h(*(const float4*)src, *(const float4*)(src + 4));
        }
        __syncthreads();
#pragma unroll
        for (int kk = 0; kk < 4; kk++) {
            uint32_t a[4];
            ldm_x4(a, As + arow * 72 + kk * 16 + acoff);
#pragma unroll
            for (int dtp = 0; dtp < 2; dtp++) {
                uint32_t b[4];
                ldm_x4_trans(b, Ws + (kk * 16 + brow) * 72 + wc * 32 + dtp * 16 + bcoff);
                mma_f16(o[2 * dtp],     a[0], a[1], a[2], a[3], b[0], b[1]);
                mma_f16(o[2 * dtp + 1], a[0], a[1], a[2], a[3], b[2], b[3]);
            }
        }
    }

    const int r = row0 + wr * 16 + g;
#pragma unroll
    for (int nt = 0; nt < 4; nt++) {
        int c = col0 + wc * 32 + nt * 8 + 2 * q;
        float b0 = bias[c], b1 = bias[c + 1];
        *(float2*)&C[r * 256 + c] = make_float2(o[nt][0] + b0, o[nt][1] + b1);
        *(float2*)&C[(r + 8) * 256 + c] = make_float2(o[nt][2] + b0, o[nt][3] + b1);
    }
}

extern "C" void kernel_launch(void* const* d_in, const int* in_sizes, int n_in,
                              void* d_out, int out_size) {
    Ptrs ptrs;
    for (int i = 0; i < 16; i++) ptrs.p[i] = (const float*)d_in[i];
    float* out = (float*)d_out;

    const int fused_smem = 12 * SLOT * 2;   // 110592 B = 108 KB
    cudaFuncSetAttribute(fused_dir_kernel, cudaFuncAttributeMaxDynamicSharedMemorySize,
                         fused_smem);

    {
        dim3 grid(512 / 64, Nn / 128, 4);
        proj_f16_kernel<<<grid, 256>>>(ptrs);
    }
    {
        dim3 grid(Nn / 128, NHEADS, 4);
        fused_dir_kernel<<<grid, 256, fused_smem>>>();
    }
    recip_kernel<<<128, 256>>>();
    {
        dim3 grid(256 / 64, Nn / 64, 2);
        outproj_f16_kernel<<<grid, 256>>>(ptrs, out);
    }
}

// round 15
// speedup vs baseline: 1.1512x; 1.0015x over previous
#include <cuda_runtime.h>
#include <cuda_fp16.h>
#include <math.h>
#include <stdint.h>

#define Nn 4096
#define NHEADS 8
#define SQFC 0.42466090f   // sqrt(SCALE * log2(e))
#define FULLM 0xffffffffu

// fp16 projections (K1/K2 pre-scaled by SQFC)
__device__ __half g_K1H[Nn * 512];
__device__ __half g_K2H[Nn * 512];
__device__ __half g_V1H[Nn * 512];
__device__ __half g_V2H[Nn * 512];
// fp16 partial attention outputs: slab z = dir*2 + ks
__device__ __half g_Oph[4][Nn * 512];
// per-slab row-sum partials (direct store, no atomics/zeroing)
__device__ float g_sumP[4][NHEADS * Nn];
__device__ float g_rsum[NHEADS * Nn];   // holds 1/rowsum after recip
__device__ float g_csum[NHEADS * Nn];   // holds 1/colsum after recip

struct Ptrs {
    const float* p[16];
};

__device__ __forceinline__ void mma_f16(float c[4],
                                        uint32_t a0, uint32_t a1, uint32_t a2, uint32_t a3,
                                        uint32_t b0, uint32_t b1) {
    asm volatile(
        "mma.sync.aligned.m16n8k16.row.col.f32.f16.f16.f32 "
        "{%0,%1,%2,%3}, {%4,%5,%6,%7}, {%8,%9}, {%0,%1,%2,%3};\n"
        : "+f"(c[0]), "+f"(c[1]), "+f"(c[2]), "+f"(c[3])
        : "r"(a0), "r"(a1), "r"(a2), "r"(a3), "r"(b0), "r"(b1));
}

// f16-accumulator variant: D/C are 2 packed f16x2 regs
__device__ __forceinline__ void mma_f16h(uint32_t c[2],
                                         uint32_t a0, uint32_t a1, uint32_t a2, uint32_t a3,
                                         uint32_t b0, uint32_t b1) {
    asm volatile(
        "mma.sync.aligned.m16n8k16.row.col.f16.f16.f16.f16 "
        "{%0,%1}, {%2,%3,%4,%5}, {%6,%7}, {%0,%1};\n"
        : "+r"(c[0]), "+r"(c[1])
        : "r"(a0), "r"(a1), "r"(a2), "r"(a3), "r"(b0), "r"(b1));
}

__device__ __forceinline__ void ldm_x4(uint32_t r[4], const void* ptr) {
    uint32_t addr = (uint32_t)__cvta_generic_to_shared(ptr);
    asm volatile("ldmatrix.sync.aligned.m8n8.x4.shared.b16 {%0,%1,%2,%3}, [%4];"
                 : "=r"(r[0]), "=r"(r[1]), "=r"(r[2]), "=r"(r[3]) : "r"(addr));
}

__device__ __forceinline__ void ldm_x4_trans(uint32_t r[4], const void* ptr) {
    uint32_t addr = (uint32_t)__cvta_generic_to_shared(ptr);
    asm volatile("ldmatrix.sync.aligned.m8n8.x4.trans.shared.b16 {%0,%1,%2,%3}, [%4];"
                 : "=r"(r[0]), "=r"(r[1]), "=r"(r[2]), "=r"(r[3]) : "r"(addr));
}

__device__ __forceinline__ void cp16(void* smem_dst, const void* gsrc) {
    uint32_t d = (uint32_t)__cvta_generic_to_shared(smem_dst);
    asm volatile("cp.async.cg.shared.global [%0], [%1], 16;" :: "r"(d), "l"(gsrc));
}

__device__ __forceinline__ uint32_t ex2p(uint32_t h2) {
    uint32_t r;
    asm("ex2.approx.f16x2 %0, %1;" : "=r"(r) : "r"(h2));
    return r;
}

__device__ __forceinline__ uint4 pack8h(float4 v0, float4 v1) {
    uint4 u;
    __half2* h = (__half2*)&u;
    h[0] = __floats2half2_rn(v0.x, v0.y);
    h[1] = __floats2half2_rn(v0.z, v0.w);
    h[2] = __floats2half2_rn(v1.x, v1.y);
    h[3] = __floats2half2_rn(v1.z, v1.w);
    return u;
}

// ---------------------------------------------------------------------------
__global__ void recip_kernel() {
    int i = blockIdx.x * 256 + threadIdx.x;   // 32768
    g_rsum[i] = 1.0f / (g_sumP[0][i] + g_sumP[1][i]);
    g_csum[i] = 1.0f / (g_sumP[2][i] + g_sumP[3][i]);
}

// ---------------------------------------------------------------------------
// Projection (fp16 mma): C = A @ W + bias -> fp16; K1/K2 scaled by SQFC.
// grid (8, 32, 4), 256 thr.
// ---------------------------------------------------------------------------
__global__ __launch_bounds__(256) void proj_f16_kernel(Ptrs in) {
    const float *A, *W, *bias;
    __half* C;
    float sc;
    switch (blockIdx.z) {
        case 0: A = in.p[0]; W = in.p[4];  bias = in.p[5];  C = g_K1H; sc = SQFC; break;
        case 1: A = in.p[1]; W = in.p[6];  bias = in.p[7];  C = g_V1H; sc = 1.0f; break;
        case 2: A = in.p[2]; W = in.p[8];  bias = in.p[9];  C = g_K2H; sc = SQFC; break;
        default:A = in.p[3]; W = in.p[10]; bias = in.p[11]; C = g_V2H; sc = 1.0f; break;
    }
    __shared__ __half As[128 * 72];
    __shared__ __half Ws[64 * 72];

    const int tid = threadIdx.x;
    const int lane = tid & 31, wid = tid >> 5;
    const int q = lane & 3, g = lane >> 2;
    const int row0 = blockIdx.y * 128;
    const int col0 = blockIdx.x * 64;
    const int brow = ((lane >> 3) & 1) * 8 + (lane & 7);
    const int bcoff = (lane >> 4) * 8;
    const int arow = wid * 16 + (lane & 7) + ((lane >> 3) & 1) * 8;
    const int acoff = (lane >> 4) * 8;

    float o[8][4];
#pragma unroll
    for (int nt = 0; nt < 8; nt++)
#pragma unroll
        for (int j = 0; j < 4; j++) o[nt][j] = 0.f;

    for (int k0 = 0; k0 < 256; k0 += 64) {
        __syncthreads();
#pragma unroll
        for (int it = 0; it < 4; it++) {
            int j = tid + it * 256;
            int rr = j >> 3, c8 = j & 7;
            const float* src = &A[(row0 + rr) * 256 + k0 + c8 * 8];
            *(uint4*)&As[rr * 72 + c8 * 8] =
                pack8h(*(const float4*)src, *(const float4*)(src + 4));
        }
#pragma unroll
        for (int it = 0; it < 2; it++) {
            int j = tid + it * 256;
            int rr = j >> 3, c8 = j & 7;
            const float* src = &W[(k0 + rr) * 512 + col0 + c8 * 8];
            *(uint4*)&Ws[rr * 72 + c8 * 8] =
                pack8h(*(const float4*)src, *(const float4*)(src + 4));
        }
        __syncthreads();
#pragma unroll
        for (int kk = 0; kk < 4; kk++) {
            uint32_t a[4];
            ldm_x4(a, As + arow * 72 + kk * 16 + acoff);
#pragma unroll
            for (int dtp = 0; dtp < 4; dtp++) {
                uint32_t b[4];
                ldm_x4_trans(b, Ws + (kk * 16 + brow) * 72 + dtp * 16 + bcoff);
                mma_f16(o[2 * dtp],     a[0], a[1], a[2], a[3], b[0], b[1]);
                mma_f16(o[2 * dtp + 1], a[0], a[1], a[2], a[3], b[2], b[3]);
            }
        }
    }

    const int r = row0 + wid * 16 + g;
#pragma unroll
    for (int nt = 0; nt < 8; nt++) {
        int c = col0 + nt * 8 + 2 * q;
        float b0 = bias[c], b1 = bias[c + 1];
        __half2 h0 = __floats2half2_rn((o[nt][0] + b0) * sc, (o[nt][1] + b1) * sc);
        __half2 h1 = __floats2half2_rn((o[nt][2] + b0) * sc, (o[nt][3] + b1) * sc);
        *(uint32_t*)&C[r * 512 + c] = *(uint32_t*)&h0;
        *(uint32_t*)&C[(r + 8) * 512 + c] = *(uint32_t*)&h1;
    }
}

// ---------------------------------------------------------------------------
// Fused dual attention: register-resident P, 6-slot cp.async ring,
// TWO 64-key tiles per __syncthreads (16 barriers total).
// grid (32, 8, 4): z = dir*2 + ks. 108KB smem, occ 2.
// ---------------------------------------------------------------------------
#define SLOT 4608   // halves per tile slot (64 rows x 72)

__global__ __launch_bounds__(256, 2) void fused_dir_kernel() {
    extern __shared__ __half sm[];
    __half* Kb = sm;                 // 6 slots; slots 0-1 double as Q staging at init
    __half* Vb = sm + 6 * SLOT;      // 6 slots

    const int n0 = blockIdx.x * 128;
    const int head = blockIdx.y;
    const int hc = head * 64;
    const int z = blockIdx.z;
    const int dir = z >> 1;
    const int ks = z & 1;

    const __half* Qg = dir ? g_K2H : g_K1H;
    const __half* Kg = dir ? g_K1H : g_K2H;
    const __half* Vg = dir ? g_V1H : g_V2H;

    const int tid = threadIdx.x;
    const int lane = tid & 31, wid = tid >> 5;
    const int q = lane & 3, g = lane >> 2;
    const int arow_lm = wid * 16 + (lane & 7) + ((lane >> 3) & 1) * 8;
    const int acoff = (lane >> 4) * 8;
    const int brow2 = ((lane >> 3) & 1) * 8 + (lane & 7);
    const int bcoff = (lane >> 4) * 8;
    const int arow = wid * 16 + g;

    // ---- stage Q in Kb slots 0-1, build A-fragments ----
#pragma unroll
    for (int it = 0; it < 4; it++) {
        int j = tid + it * 256;
        int rr = j >> 3, c8 = j & 7;
        cp16(Kb + rr * 72 + c8 * 8, Qg + (n0 + rr) * 512 + hc + c8 * 8);
    }
    asm volatile("cp.async.commit_group;" ::: "memory");
    asm volatile("cp.async.wait_group 0;" ::: "memory");
    __syncthreads();

    uint32_t af[4][4];
#pragma unroll
    for (int kk = 0; kk < 4; kk++)
        ldm_x4(af[kk], Kb + arow_lm * 72 + kk * 16 + acoff);
    __syncthreads();   // Q staging free

    // issue one group = two consecutive stages (2g, 2g+1)
    auto issue2 = [&](int grp) {
#pragma unroll
        for (int e = 0; e < 2; e++) {
            const int s = 2 * grp + e;
            const int m0 = (ks * 32 + s) * 64;
            __half* Kd = Kb + (s % 6) * SLOT;
            __half* Vd = Vb + (s % 6) * SLOT;
#pragma unroll
            for (int it = 0; it < 2; it++) {
                int j = tid + it * 256;
                int rr = j >> 3, c8 = j & 7;
                cp16(Kd + rr * 72 + c8 * 8, Kg + (m0 + rr) * 512 + hc + c8 * 8);
                cp16(Vd + rr * 72 + c8 * 8, Vg + (m0 + rr) * 512 + hc + c8 * 8);
            }
        }
        asm volatile("cp.async.commit_group;" ::: "memory");
    };

    issue2(0);
    issue2(1);

    float o[8][4];
#pragma unroll
    for (int dt = 0; dt < 8; dt++)
#pragma unroll
        for (int j = 0; j < 4; j++) o[dt][j] = 0.f;
    float rloc0 = 0.f, rloc1 = 0.f;

    // process one 64-key tile from the given slot
    auto process = [&](int slot) {
        const __half* Kc = Kb + slot * SLOT;
        const __half* Vc = Vb + slot * SLOT;

        uint32_t p[4][4];
        __half2 hsA = __floats2half2_rn(0.f, 0.f);
        __half2 hsB = hsA;
#pragma unroll
        for (int nt2 = 0; nt2 < 4; nt2++) {
            uint32_t s0[2] = {0u, 0u};
            uint32_t s1[2] = {0u, 0u};
#pragma unroll
            for (int kk = 0; kk < 4; kk++) {
                uint32_t bq[4];
                ldm_x4(bq, Kc + (nt2 * 16 + brow2) * 72 + kk * 16 + bcoff);
                mma_f16h(s0, af[kk][0], af[kk][1], af[kk][2], af[kk][3], bq[0], bq[2]);
                mma_f16h(s1, af[kk][0], af[kk][1], af[kk][2], af[kk][3], bq[1], bq[3]);
            }
            p[nt2][0] = ex2p(s0[0]);
            p[nt2][1] = ex2p(s0[1]);
            p[nt2][2] = ex2p(s1[0]);
            p[nt2][3] = ex2p(s1[1]);
            hsA = __hadd2(hsA, __hadd2(*(__half2*)&p[nt2][0], *(__half2*)&p[nt2][2]));
            hsB = __hadd2(hsB, __hadd2(*(__half2*)&p[nt2][1], *(__half2*)&p[nt2][3]));
        }
        float2 fA = __half22float2(hsA);
        float2 fB = __half22float2(hsB);
        rloc0 += fA.x + fA.y;
        rloc1 += fB.x + fB.y;

#pragma unroll
        for (int kc = 0; kc < 4; kc++) {
#pragma unroll
            for (int dtp = 0; dtp < 4; dtp++) {
                uint32_t b[4];
                ldm_x4_trans(b, Vc + (kc * 16 + brow2) * 72 + dtp * 16 + bcoff);
                mma_f16(o[2 * dtp],     p[kc][0], p[kc][1], p[kc][2], p[kc][3], b[0], b[1]);
                mma_f16(o[2 * dtp + 1], p[kc][0], p[kc][1], p[kc][2], p[kc][3], b[2], b[3]);
            }
        }
    };

    for (int grp = 0; grp < 16; grp++) {
        if (grp == 15) asm volatile("cp.async.wait_group 0;" ::: "memory");
        else           asm volatile("cp.async.wait_group 1;" ::: "memory");
        __syncthreads();   // group grp visible; group grp-1 slots free everywhere

        if (grp + 2 < 16) issue2(grp + 2);   // targets slots of group grp-1

        process((2 * grp) % 6);
        process((2 * grp + 1) % 6);
    }

    // ---- flush partial o (fp16 direct store) + row-sum partials ----
    {
        const int rN = n0 + arow;
        __half* Og = g_Oph[z] + rN * 512 + hc;
#pragma unroll
        for (int dt = 0; dt < 8; dt++) {
            __half2 h0 = __floats2half2_rn(o[dt][0], o[dt][1]);
            __half2 h1 = __floats2half2_rn(o[dt][2], o[dt][3]);
            *(uint32_t*)&Og[dt * 8 + 2 * q] = *(uint32_t*)&h0;
            *(uint32_t*)&Og[8 * 512 + dt * 8 + 2 * q] = *(uint32_t*)&h1;
        }
    }
    rloc0 += __shfl_xor_sync(FULLM, rloc0, 1);
    rloc0 += __shfl_xor_sync(FULLM, rloc0, 2);
    rloc1 += __shfl_xor_sync(FULLM, rloc1, 1);
    rloc1 += __shfl_xor_sync(FULLM, rloc1, 2);
    if (q == 0) {
        g_sumP[z][head * Nn + n0 + arow] = rloc0;
        g_sumP[z][head * Nn + n0 + arow + 8] = rloc1;
    }
}

// ---------------------------------------------------------------------------
// Output GEMM (fp16 mma): out = ((S0+S1) * inv) @ Wo + bias.
// BM=64: grid (4, 64, 2) = 512 CTAs; warps 4(row) x 2(col), warp tile 16x32.
// ---------------------------------------------------------------------------
__global__ __launch_bounds__(256) void outproj_f16_kernel(Ptrs in, float* out) {
    const __half *S0h, *S1h;
    const float *inv, *W, *bias;
    float* C;
    if (blockIdx.z == 0) {
        S0h = g_Oph[2]; S1h = g_Oph[3]; inv = g_csum;
        W = in.p[12]; bias = in.p[13]; C = out;
    } else {
        S0h = g_Oph[0]; S1h = g_Oph[1]; inv = g_rsum;
        W = in.p[14]; bias = in.p[15]; C = out + Nn * 256;
    }
    __shared__ __half As[64 * 72];
    __shared__ __half Ws[64 * 72];

    const int tid = threadIdx.x;
    const int lane = tid & 31, wid = tid >> 5;
    const int q = lane & 3, g = lane >> 2;
    const int wr = wid & 3, wc = wid >> 2;
    const int row0 = blockIdx.y * 64;
    const int col0 = blockIdx.x * 64;
    const int brow = ((lane >> 3) & 1) * 8 + (lane & 7);
    const int bcoff = (lane >> 4) * 8;
    const int arow = wr * 16 + (lane & 7) + ((lane >> 3) & 1) * 8;
    const int acoff = (lane >> 4) * 8;

    float o[4][4];
#pragma unroll
    for (int nt = 0; nt < 4; nt++)
#pragma unroll
        for (int j = 0; j < 4; j++) o[nt][j] = 0.f;

    for (int k0 = 0; k0 < 512; k0 += 64) {
        const int head = k0 >> 6;
        __syncthreads();
#pragma unroll
        for (int it = 0; it < 2; it++) {
            int j = tid + it * 256;
            int rr = j >> 3, c8 = j & 7;
            int idx = (row0 + rr) * 512 + k0 + c8 * 8;
            float iv = inv[head * Nn + row0 + rr];
            uint4 u0 = *(const uint4*)&S0h[idx];
            uint4 u1 = *(const uint4*)&S1h[idx];
            const __half2* h0 = (const __half2*)&u0;
            const __half2* h1 = (const __half2*)&u1;
            uint4 uo;
            __half2* ho = (__half2*)&uo;
#pragma unroll
            for (int e = 0; e < 4; e++) {
                float2 f0 = __half22float2(h0[e]);
                float2 f1 = __half22float2(h1[e]);
                ho[e] = __floats2half2_rn((f0.x + f1.x) * iv, (f0.y + f1.y) * iv);
            }
            *(uint4*)&As[rr * 72 + c8 * 8] = uo;
        }
#pragma unroll
        for (int it = 0; it < 2; it++) {
            int j = tid + it * 256;
            int rr = j >> 3, c8 = j & 7;
            const float* src = &W[(k0 + rr) * 256 + col0 + c8 * 8];
            *(uint4*)&Ws[rr * 72 + c8 * 8] =
                pack8h(*(const float4*)src, *(const float4*)(src + 4));
        }
        __syncthreads();
#pragma unroll
        for (int kk = 0; kk < 4; kk++) {
            uint32_t a[4];
            ldm_x4(a, As + arow * 72 + kk * 16 + acoff);
#pragma unroll
            for (int dtp = 0; dtp < 2; dtp++) {
                uint32_t b[4];
                ldm_x4_trans(b, Ws + (kk * 16 + brow) * 72 + wc * 32 + dtp * 16 + bcoff);
                mma_f16(o[2 * dtp],     a[0], a[1], a[2], a[3], b[0], b[1]);
                mma_f16(o[2 * dtp + 1], a[0], a[1], a[2], a[3], b[2], b[3]);
            }
        }
    }

    const int r = row0 + wr * 16 + g;
#pragma unroll
    for (int nt = 0; nt < 4; nt++) {
        int c = col0 + wc * 32 + nt * 8 + 2 * q;
        float b0 = bias[c], b1 = bias[c + 1];
        *(float2*)&C[r * 256 + c] = make_float2(o[nt][0] + b0, o[nt][1] + b1);
        *(float2*)&C[(r + 8) * 256 + c] = make_float2(o[nt][2] + b0, o[nt][3] + b1);
    }
}

extern "C" void kernel_launch(void* const* d_in, const int* in_sizes, int n_in,
                              void* d_out, int out_size) {
    Ptrs ptrs;
    for (int i = 0; i < 16; i++) ptrs.p[i] = (const float*)d_in[i];
    float* out = (float*)d_out;

    const int fused_smem = 12 * SLOT * 2;   // 110592 B = 108 KB
    cudaFuncSetAttribute(fused_dir_kernel, cudaFuncAttributeMaxDynamicSharedMemorySize,
                         fused_smem);

    {
        dim3 grid(512 / 64, Nn / 128, 4);
        proj_f16_kernel<<<grid, 256>>>(ptrs);
    }
    {
        dim3 grid(Nn / 128, NHEADS, 4);
        fused_dir_kernel<<<grid, 256, fused_smem>>>();
    }
    recip_kernel<<<128, 256>>>();
    {
        dim3 grid(256 / 64, Nn / 64, 2);
        outproj_f16_kernel<<<grid, 256>>>(ptrs, out);
    }
}